// round 3
// baseline (speedup 1.0000x reference)
#include <cuda_runtime.h>
#include <math.h>

// Problem constants
#define BV 512
#define TV 64
#define FV 256
#define HV 1024

// Output layout: x_imp [B,T,F] | reconstruction [B,T,F] | h_fin [B,H] | x_loss | kl_loss
#define OFF_REC   (BV*TV*FV)
#define OFF_HFIN  (2*BV*TV*FV)
#define OFF_LOSS  (2*BV*TV*FV + BV*HV)

#define NB2 32   // number of blocks in GEMM2 grid (loss partials per step)

// ---------------- scratch ----------------
__device__ float g_h[BV*HV];
__device__ float g_xh[BV*FV];
__device__ float g_gh[BV*3*HV];
__device__ float g_gi[BV*3*HV];
__device__ float g_gammaH[(size_t)TV*BV*HV];
__device__ float g_beta[(size_t)TV*BV*FV];
__device__ float g_msum[TV];
__device__ float g_lossPart[TV*NB2];

// ---------------- double-buffered tiled SGEMM: C[m,n]=sum_k A(m,k)*B(n,k) ----------------
template<int BM,int BN,int BK,int TM,int TN,class AL,class BL,class EP>
__global__ __launch_bounds__(256)
void gemm_k(int K, AL al, BL bl, EP ep) {
    constexpr int TH = (BM/TM)*(BN/TN);
    static_assert(TH == 256, "thread count");
    constexpr int AE = BM*BK/TH;      // per-thread A elements per tile
    constexpr int BE = BN*BK/TH;

    __shared__ float As[2][BK][BM+4];
    __shared__ float Bs[2][BK][BN+4];

    const int tid = threadIdx.x;
    const int bm = blockIdx.y * BM;
    const int bn = blockIdx.x * BN;
    const int tx = tid % (BN/TN);
    const int ty = tid / (BN/TN);

    float acc[TM][TN];
    #pragma unroll
    for (int i = 0; i < TM; i++)
        #pragma unroll
        for (int j = 0; j < TN; j++) acc[i][j] = 0.f;

    float ar[AE], br[BE];

    // prologue: load tile 0 into regs, store to buffer 0
    #pragma unroll
    for (int i = 0; i < AE; i++) { int e = tid + i*TH; ar[i] = al(bm + e/BK, e % BK); }
    #pragma unroll
    for (int i = 0; i < BE; i++) { int e = tid + i*TH; br[i] = bl(bn + e/BK, e % BK); }
    #pragma unroll
    for (int i = 0; i < AE; i++) { int e = tid + i*TH; As[0][e % BK][e/BK] = ar[i]; }
    #pragma unroll
    for (int i = 0; i < BE; i++) { int e = tid + i*TH; Bs[0][e % BK][e/BK] = br[i]; }
    __syncthreads();

    int cur = 0;
    for (int k0 = BK; k0 <= K; k0 += BK) {
        const bool more = (k0 < K);
        // prefetch next tile into registers (overlaps with compute below)
        if (more) {
            #pragma unroll
            for (int i = 0; i < AE; i++) { int e = tid + i*TH; ar[i] = al(bm + e/BK, k0 + e % BK); }
            #pragma unroll
            for (int i = 0; i < BE; i++) { int e = tid + i*TH; br[i] = bl(bn + e/BK, k0 + e % BK); }
        }
        // compute current tile
        #pragma unroll
        for (int kk = 0; kk < BK; kk++) {
            float a[TM], b[TN];
            #pragma unroll
            for (int i = 0; i < TM; i += 4) {
                float4 v = *(const float4*)&As[cur][kk][ty*TM + i];
                a[i] = v.x; a[i+1] = v.y; a[i+2] = v.z; a[i+3] = v.w;
            }
            #pragma unroll
            for (int j = 0; j < TN; j += 4) {
                float4 v = *(const float4*)&Bs[cur][kk][tx*TN + j];
                b[j] = v.x; b[j+1] = v.y; b[j+2] = v.z; b[j+3] = v.w;
            }
            #pragma unroll
            for (int i = 0; i < TM; i++)
                #pragma unroll
                for (int j = 0; j < TN; j++)
                    acc[i][j] = fmaf(a[i], b[j], acc[i][j]);
        }
        // stage next tile into the other buffer
        if (more) {
            #pragma unroll
            for (int i = 0; i < AE; i++) { int e = tid + i*TH; As[cur^1][e % BK][e/BK] = ar[i]; }
            #pragma unroll
            for (int i = 0; i < BE; i++) { int e = tid + i*TH; Bs[cur^1][e % BK][e/BK] = br[i]; }
        }
        __syncthreads();
        cur ^= 1;
    }

    float rsum = 0.f;
    #pragma unroll
    for (int i = 0; i < TM; i++) {
        int gm = bm + ty*TM + i;
        #pragma unroll
        for (int j = 0; j < TN; j++) {
            int gn = bn + tx*TN + j;
            rsum += ep(gm, gn, acc[i][j]);
        }
    }

    if constexpr (EP::RED) {
        __shared__ float red[256];
        red[tid] = rsum;
        __syncthreads();
        for (int s = 128; s > 0; s >>= 1) {
            if (tid < s) red[tid] += red[tid + s];
            __syncthreads();
        }
        if (tid == 0) {
            int lin = blockIdx.y * gridDim.x + blockIdx.x;
            ep.store_partial(lin, red[0]);
        }
    }
}

// ---------------- functors ----------------

// P1: gammaH = exp(-relu(deltas @ Wdh^T + bdh)); M = T*B (m = t*B + b)
struct AL_P1 {
    const float* deltas;
    __device__ float operator()(int m, int k) const {
        int t = m >> 9, b = m & 511;
        return deltas[(b*TV + t)*FV + k];
    }
};
struct BL_P1 {
    const float* Wdh;
    __device__ float operator()(int n, int k) const { return Wdh[n*FV + k]; }
};
struct EP_P1 {
    const float* bdh;
    static constexpr bool RED = false;
    __device__ float operator()(int m, int n, float v) const {
        g_gammaH[(size_t)m*HV + n] = expf(-fmaxf(v + bdh[n], 0.f));
        return 0.f;
    }
    __device__ void store_partial(int, float) const {}
};

// P2: beta = [gamma_x, m] @ Wwc^T + bwc; gamma_x computed on the fly (diag decay)
struct AL_P2 {
    const float* deltas; const float* mask; const float* Wdx; const float* bdx;
    __device__ float operator()(int m, int k) const {
        int t = m >> 9, b = m & 511;
        if (k < FV) {
            float d = deltas[(b*TV + t)*FV + k];
            return expf(-fmaxf(d * Wdx[k*FV + k] + bdx[k], 0.f));
        }
        return mask[(b*TV + t)*FV + (k - FV)];
    }
};
struct BL_P2 {
    const float* Wwc;
    __device__ float operator()(int n, int k) const { return Wwc[n*(2*FV) + k]; }
};
struct EP_P2 {
    const float* bwc;
    static constexpr bool RED = false;
    __device__ float operator()(int m, int n, float v) const {
        g_beta[(size_t)m*FV + n] = v + bwc[n];
        return 0.f;
    }
    __device__ void store_partial(int, float) const {}
};

// G1: [x_h | gh] = (h * gammaH[t]) @ [Wh ; Whh]^T  (N = 3328, K = 1024)
struct AL_G1 {
    int t;
    __device__ float operator()(int m, int k) const {
        int idx = m*HV + k;
        return g_h[idx] * g_gammaH[(size_t)t*BV*HV + idx];
    }
};
struct BL_G1 {
    const float* Wh; const float* Whh;
    __device__ float operator()(int n, int k) const {
        return (n < FV) ? Wh[n*HV + k] : Whh[(n - FV)*HV + k];
    }
};
struct EP_G1 {
    const float* bh; const float* bhh;
    static constexpr bool RED = false;
    __device__ float operator()(int m, int n, float v) const {
        if (n < FV) g_xh[m*FV + n] = v + bh[n];
        else        g_gh[m*3*HV + (n - FV)] = v + bhh[n - FV];
        return 0.f;
    }
    __device__ void store_partial(int, float) const {}
};

// G2: xu = x_r @ Wfr_off^T + bfr ; epilogue: combine, imputation, loss partial
struct AL_G2 {
    const float* x; const float* mask; int t;
    __device__ float operator()(int m, int k) const {
        int idx = (m*TV + t)*FV + k;
        float mt = mask[idx];
        return mt * x[idx] + (1.f - mt) * g_xh[m*FV + k];
    }
};
struct BL_G2 {
    const float* Wfr;
    __device__ float operator()(int n, int k) const {
        return (n == k) ? 0.f : Wfr[n*FV + k];
    }
};
struct EP_G2 {
    const float* bfr; const float* x; const float* mask;
    float* rec; float* ximp; int t;
    static constexpr bool RED = true;
    __device__ float operator()(int m, int n, float v) const {
        float xu = v + bfr[n];
        float xh = g_xh[m*FV + n];
        float be = g_beta[(size_t)t*BV*FV + m*FV + n];
        float xc = be * xu + (1.f - be) * xh;
        int idx = (m*TV + t)*FV + n;
        float mt = mask[idx], xt = x[idx];
        rec[idx]  = xc;
        ximp[idx] = mt * xt + (1.f - mt) * xc;
        return fabsf(xc - xt) * mt;
    }
    __device__ void store_partial(int lin, float v) const {
        g_lossPart[t*NB2 + lin] = v;
    }
};

// G3: gi = [x_imp, m] @ Wih^T + bih  (K = 512)
struct AL_G3 {
    const float* ximp; const float* mask; int t;
    __device__ float operator()(int m, int k) const {
        if (k < FV) return ximp[(m*TV + t)*FV + k];
        return mask[(m*TV + t)*FV + (k - FV)];
    }
};
struct BL_G3 {
    const float* Wih;
    __device__ float operator()(int n, int k) const { return Wih[n*(2*FV) + k]; }
};
struct EP_G3 {
    const float* bih;
    static constexpr bool RED = false;
    __device__ float operator()(int m, int n, float v) const {
        g_gi[m*3*HV + n] = v + bih[n];
        return 0.f;
    }
    __device__ void store_partial(int, float) const {}
};

// ---------------- elementwise kernels ----------------

__global__ void hinit_k(const float* __restrict__ h0) {
    int idx = blockIdx.x * blockDim.x + threadIdx.x;
    if (idx < BV*HV) g_h[idx] = h0[idx];
}

__global__ void msum_k(const float* __restrict__ mask) {
    int t = blockIdx.x;
    float s = 0.f;
    for (int i = threadIdx.x; i < BV*FV; i += 256) {
        int b = i >> 8, f = i & 255;
        s += mask[(b*TV + t)*FV + f];
    }
    __shared__ float red[256];
    red[threadIdx.x] = s;
    __syncthreads();
    for (int st = 128; st > 0; st >>= 1) {
        if (threadIdx.x < st) red[threadIdx.x] += red[threadIdx.x + st];
        __syncthreads();
    }
    if (threadIdx.x == 0) g_msum[t] = red[0];
}

__global__ void gru_k(int t, float* __restrict__ hfin) {
    int idx = blockIdx.x * blockDim.x + threadIdx.x;  // B*H
    int b = idx >> 10, j = idx & 1023;
    float hd = g_h[idx] * g_gammaH[(size_t)t*BV*HV + idx];
    int base = b*3*HV + j;
    float r = 1.f / (1.f + expf(-(g_gi[base]        + g_gh[base])));
    float z = 1.f / (1.f + expf(-(g_gi[base + HV]   + g_gh[base + HV])));
    float n = tanhf(g_gi[base + 2*HV] + r * g_gh[base + 2*HV]);
    float hn = (1.f - z) * n + z * hd;
    g_h[idx] = hn;
    if (hfin) hfin[idx] = hn;
}

__global__ void final_k(float* __restrict__ out) {
    __shared__ float s[TV];
    int t = threadIdx.x;  // 64 threads
    float acc = 0.f;
    for (int i = 0; i < NB2; i++) acc += g_lossPart[t*NB2 + i];
    s[t] = acc / (g_msum[t] + 1e-12f);
    __syncthreads();
    if (t == 0) {
        float L = 0.f;
        for (int i = 0; i < TV; i++) L += s[i];
        out[OFF_LOSS]     = L;
        out[OFF_LOSS + 1] = 0.f;  // kl_loss
    }
}

// ---------------- launch ----------------

extern "C" void kernel_launch(void* const* d_in, const int* in_sizes, int n_in,
                              void* d_out, int out_size) {
    const float* x      = (const float*)d_in[0];
    const float* mask   = (const float*)d_in[1];
    const float* deltas = (const float*)d_in[2];
    const float* h0     = (const float*)d_in[3];
    const float* Wdh    = (const float*)d_in[4];
    const float* bdh    = (const float*)d_in[5];
    const float* Wdx    = (const float*)d_in[6];
    const float* bdx    = (const float*)d_in[7];
    const float* Wh     = (const float*)d_in[8];
    const float* bh     = (const float*)d_in[9];
    const float* Wfr    = (const float*)d_in[10];
    const float* bfr    = (const float*)d_in[11];
    const float* Wwc    = (const float*)d_in[12];
    const float* bwc    = (const float*)d_in[13];
    const float* Wih    = (const float*)d_in[14];
    const float* bih    = (const float*)d_in[15];
    const float* Whh    = (const float*)d_in[16];
    const float* bhh    = (const float*)d_in[17];

    float* out      = (float*)d_out;
    float* ximp_out = out;
    float* rec_out  = out + OFF_REC;
    float* hfin     = out + OFF_HFIN;

    hinit_k<<<(BV*HV)/256, 256>>>(h0);
    msum_k<<<TV, 256>>>(mask);

    // Precompute gammaH: M=32768, N=1024, K=256 (2048 blocks)
    gemm_k<128,128,16,8,8><<<dim3(1024/128, 32768/128), 256>>>(
        FV, AL_P1{deltas}, BL_P1{Wdh}, EP_P1{bdh});

    // Precompute beta: M=32768, N=256, K=512 (512 blocks)
    gemm_k<128,128,16,8,8><<<dim3(256/128, 32768/128), 256>>>(
        2*FV, AL_P2{deltas, mask, Wdx, bdx}, BL_P2{Wwc}, EP_P2{bwc});

    for (int t = 0; t < TV; t++) {
        // G1: [x_h | gh], M=512, N=3328, K=1024 -> 26 x 8 = 208 blocks
        gemm_k<64,128,16,4,8><<<dim3(3328/128, 512/64), 256>>>(
            HV, AL_G1{t}, BL_G1{Wh, Whh}, EP_G1{bh, bhh});

        // G2: xu + fused combine/imputation/loss, M=512, N=256, K=256 (32 blocks)
        gemm_k<64,64,16,4,4><<<dim3(256/64, 512/64), 256>>>(
            FV, AL_G2{x, mask, t}, BL_G2{Wfr},
            EP_G2{bfr, x, mask, rec_out, ximp_out, t});

        // G3: gi, M=512, N=3072, K=512 -> 24 x 8 = 192 blocks
        gemm_k<64,128,16,4,8><<<dim3(3072/128, 512/64), 256>>>(
            2*FV, AL_G3{ximp_out, mask, t}, BL_G3{Wih}, EP_G3{bih});

        // GRU elementwise update
        gru_k<<<(BV*HV)/256, 256>>>(t, (t == TV-1) ? hfin : nullptr);
    }

    final_k<<<1, TV>>>(out);
}

// round 4
// speedup vs baseline: 2.3180x; 2.3180x over previous
#include <cuda_runtime.h>
#include <math.h>
#include <stdint.h>

// Problem constants
#define BV 512
#define TV 64
#define FV 256
#define HV 1024

// Output layout: x_imp [B,T,F] | reconstruction [B,T,F] | h_fin [B,H] | x_loss | kl_loss
#define OFF_REC   (BV*TV*FV)
#define OFF_HFIN  (2*BV*TV*FV)
#define OFF_LOSS  (2*BV*TV*FV + BV*HV)

#define NB2 32   // number of blocks in GEMM2 grid (loss partials per step)

// ---------------- scratch ----------------
__device__ float g_h[BV*HV];
__device__ float g_xh[BV*FV];
__device__ float g_gh[BV*3*HV];
__device__ float g_gi[BV*3*HV];
__device__ float g_gammaH[(size_t)TV*BV*HV];
__device__ float g_beta[(size_t)TV*BV*FV];
__device__ float g_msum[TV];
__device__ float g_lossPart[TV*NB2];

__device__ __forceinline__ uint32_t f2tf(float f) {
    uint32_t r;
    asm("cvt.rna.tf32.f32 %0, %1;" : "=r"(r) : "f"(f));
    return r;
}

// ------------- tf32 tensor-core GEMM: C[m,n] = sum_k A(m,k)*B(n,k), fused epilogue -------------
// 256 threads = 8 warps, warp grid (BM/WM) x (BN/WN). mma.sync.m16n8k8 tf32.
template<int BM,int BN,int BK,int WM,int WN,class AL,class BL,class EP>
__global__ __launch_bounds__(256, 2)
void tgemm_k(int K, AL al, BL bl, EP ep) {
    constexpr int WARPS_M = BM/WM, WARPS_N = BN/WN;
    static_assert(WARPS_M*WARPS_N == 8, "need 8 warps");
    constexpr int MI = WM/16, NI = WN/8;
    constexpr int TH = 256;
    constexpr int AE = BM*BK/TH, BE = BN*BK/TH;
    constexpr int LS = BK + 4;   // word stride; BK=16 -> 20 (conflict-free frag loads)

    __shared__ uint32_t As[2][BM*LS];
    __shared__ uint32_t Bs[2][BN*LS];

    const int tid = threadIdx.x;
    const int lane = tid & 31, wid = tid >> 5;
    const int wm = (wid % WARPS_M) * WM;
    const int wn = (wid / WARPS_M) * WN;
    const int gid = lane >> 2, tig = lane & 3;
    const int bm = blockIdx.y * BM, bn = blockIdx.x * BN;

    float acc[MI][NI][4];
    #pragma unroll
    for (int mi = 0; mi < MI; mi++)
        #pragma unroll
        for (int ni = 0; ni < NI; ni++)
            #pragma unroll
            for (int c = 0; c < 4; c++) acc[mi][ni][c] = 0.f;

    uint32_t ar[AE], br[BE];
    // prologue: tile 0
    #pragma unroll
    for (int i = 0; i < AE; i++) { int e = tid + i*TH; ar[i] = f2tf(al(bm + e/BK, e%BK)); }
    #pragma unroll
    for (int i = 0; i < BE; i++) { int e = tid + i*TH; br[i] = f2tf(bl(bn + e/BK, e%BK)); }
    #pragma unroll
    for (int i = 0; i < AE; i++) { int e = tid + i*TH; As[0][(e/BK)*LS + e%BK] = ar[i]; }
    #pragma unroll
    for (int i = 0; i < BE; i++) { int e = tid + i*TH; Bs[0][(e/BK)*LS + e%BK] = br[i]; }
    __syncthreads();

    int cur = 0;
    for (int k0 = BK; k0 <= K; k0 += BK) {
        const bool more = (k0 < K);
        if (more) {
            #pragma unroll
            for (int i = 0; i < AE; i++) { int e = tid + i*TH; ar[i] = f2tf(al(bm + e/BK, k0 + e%BK)); }
            #pragma unroll
            for (int i = 0; i < BE; i++) { int e = tid + i*TH; br[i] = f2tf(bl(bn + e/BK, k0 + e%BK)); }
        }
        #pragma unroll
        for (int kk = 0; kk < BK/8; kk++) {
            uint32_t af[MI][4], bf[NI][2];
            #pragma unroll
            for (int mi = 0; mi < MI; mi++) {
                int r0 = (wm + mi*16 + gid)*LS + kk*8 + tig;
                af[mi][0] = As[cur][r0];
                af[mi][1] = As[cur][r0 + 8*LS];
                af[mi][2] = As[cur][r0 + 4];
                af[mi][3] = As[cur][r0 + 8*LS + 4];
            }
            #pragma unroll
            for (int ni = 0; ni < NI; ni++) {
                int r0 = (wn + ni*8 + gid)*LS + kk*8 + tig;
                bf[ni][0] = Bs[cur][r0];
                bf[ni][1] = Bs[cur][r0 + 4];
            }
            #pragma unroll
            for (int mi = 0; mi < MI; mi++)
                #pragma unroll
                for (int ni = 0; ni < NI; ni++)
                    asm volatile(
                        "mma.sync.aligned.m16n8k8.row.col.f32.tf32.tf32.f32 "
                        "{%0,%1,%2,%3}, {%4,%5,%6,%7}, {%8,%9}, {%0,%1,%2,%3};"
                        : "+f"(acc[mi][ni][0]), "+f"(acc[mi][ni][1]),
                          "+f"(acc[mi][ni][2]), "+f"(acc[mi][ni][3])
                        : "r"(af[mi][0]), "r"(af[mi][1]), "r"(af[mi][2]), "r"(af[mi][3]),
                          "r"(bf[ni][0]), "r"(bf[ni][1]));
        }
        if (more) {
            #pragma unroll
            for (int i = 0; i < AE; i++) { int e = tid + i*TH; As[cur^1][(e/BK)*LS + e%BK] = ar[i]; }
            #pragma unroll
            for (int i = 0; i < BE; i++) { int e = tid + i*TH; Bs[cur^1][(e/BK)*LS + e%BK] = br[i]; }
        }
        __syncthreads();
        cur ^= 1;
    }

    float rsum = 0.f;
    #pragma unroll
    for (int mi = 0; mi < MI; mi++) {
        #pragma unroll
        for (int ni = 0; ni < NI; ni++) {
            int gm0 = bm + wm + mi*16 + gid;
            int gn0 = bn + wn + ni*8 + tig*2;
            rsum += ep(gm0,     gn0,     acc[mi][ni][0]);
            rsum += ep(gm0,     gn0 + 1, acc[mi][ni][1]);
            rsum += ep(gm0 + 8, gn0,     acc[mi][ni][2]);
            rsum += ep(gm0 + 8, gn0 + 1, acc[mi][ni][3]);
        }
    }

    if constexpr (EP::RED) {
        __shared__ float red[256];
        red[tid] = rsum;
        __syncthreads();
        for (int s = 128; s > 0; s >>= 1) {
            if (tid < s) red[tid] += red[tid + s];
            __syncthreads();
        }
        if (tid == 0) {
            int lin = blockIdx.y * gridDim.x + blockIdx.x;
            ep.store_partial(lin, red[0]);
        }
    }
}

// ---------------- functors ----------------

// P1: gammaH = exp(-relu(deltas @ Wdh^T + bdh)); M = T*B (m = t*B + b)
struct AL_P1 {
    const float* deltas;
    __device__ float operator()(int m, int k) const {
        int t = m >> 9, b = m & 511;
        return deltas[(b*TV + t)*FV + k];
    }
};
struct BL_P1 {
    const float* Wdh;
    __device__ float operator()(int n, int k) const { return Wdh[n*FV + k]; }
};
struct EP_P1 {
    const float* bdh;
    static constexpr bool RED = false;
    __device__ float operator()(int m, int n, float v) const {
        g_gammaH[(size_t)m*HV + n] = expf(-fmaxf(v + bdh[n], 0.f));
        return 0.f;
    }
    __device__ void store_partial(int, float) const {}
};

// P2: beta = [gamma_x, m] @ Wwc^T + bwc; gamma_x computed on the fly (diag decay)
struct AL_P2 {
    const float* deltas; const float* mask; const float* Wdx; const float* bdx;
    __device__ float operator()(int m, int k) const {
        int t = m >> 9, b = m & 511;
        if (k < FV) {
            float d = deltas[(b*TV + t)*FV + k];
            return expf(-fmaxf(d * Wdx[k*FV + k] + bdx[k], 0.f));
        }
        return mask[(b*TV + t)*FV + (k - FV)];
    }
};
struct BL_P2 {
    const float* Wwc;
    __device__ float operator()(int n, int k) const { return Wwc[n*(2*FV) + k]; }
};
struct EP_P2 {
    const float* bwc;
    static constexpr bool RED = false;
    __device__ float operator()(int m, int n, float v) const {
        g_beta[(size_t)m*FV + n] = v + bwc[n];
        return 0.f;
    }
    __device__ void store_partial(int, float) const {}
};

// G1: [x_h | gh] = (h * gammaH[t]) @ [Wh ; Whh]^T  (N = 3328, K = 1024)
struct AL_G1 {
    int t;
    __device__ float operator()(int m, int k) const {
        int idx = m*HV + k;
        return g_h[idx] * g_gammaH[(size_t)t*BV*HV + idx];
    }
};
struct BL_G1 {
    const float* Wh; const float* Whh;
    __device__ float operator()(int n, int k) const {
        return (n < FV) ? Wh[n*HV + k] : Whh[(n - FV)*HV + k];
    }
};
struct EP_G1 {
    const float* bh; const float* bhh;
    static constexpr bool RED = false;
    __device__ float operator()(int m, int n, float v) const {
        if (n < FV) g_xh[m*FV + n] = v + bh[n];
        else        g_gh[m*3*HV + (n - FV)] = v + bhh[n - FV];
        return 0.f;
    }
    __device__ void store_partial(int, float) const {}
};

// G2: xu = x_r @ Wfr_off^T + bfr ; epilogue: combine, imputation, loss partial
struct AL_G2 {
    const float* x; const float* mask; int t;
    __device__ float operator()(int m, int k) const {
        int idx = (m*TV + t)*FV + k;
        float mt = mask[idx];
        return mt * x[idx] + (1.f - mt) * g_xh[m*FV + k];
    }
};
struct BL_G2 {
    const float* Wfr;
    __device__ float operator()(int n, int k) const {
        return (n == k) ? 0.f : Wfr[n*FV + k];
    }
};
struct EP_G2 {
    const float* bfr; const float* x; const float* mask;
    float* rec; float* ximp; int t;
    static constexpr bool RED = true;
    __device__ float operator()(int m, int n, float v) const {
        float xu = v + bfr[n];
        float xh = g_xh[m*FV + n];
        float be = g_beta[(size_t)t*BV*FV + m*FV + n];
        float xc = be * xu + (1.f - be) * xh;
        int idx = (m*TV + t)*FV + n;
        float mt = mask[idx], xt = x[idx];
        rec[idx]  = xc;
        ximp[idx] = mt * xt + (1.f - mt) * xc;
        return fabsf(xc - xt) * mt;
    }
    __device__ void store_partial(int lin, float v) const {
        g_lossPart[t*NB2 + lin] = v;
    }
};

// G3: gi = [x_imp, m] @ Wih^T + bih  (K = 512)
struct AL_G3 {
    const float* ximp; const float* mask; int t;
    __device__ float operator()(int m, int k) const {
        if (k < FV) return ximp[(m*TV + t)*FV + k];
        return mask[(m*TV + t)*FV + (k - FV)];
    }
};
struct BL_G3 {
    const float* Wih;
    __device__ float operator()(int n, int k) const { return Wih[n*(2*FV) + k]; }
};
struct EP_G3 {
    const float* bih;
    static constexpr bool RED = false;
    __device__ float operator()(int m, int n, float v) const {
        g_gi[m*3*HV + n] = v + bih[n];
        return 0.f;
    }
    __device__ void store_partial(int, float) const {}
};

// ---------------- elementwise kernels ----------------

__global__ void hinit_k(const float* __restrict__ h0) {
    int idx = blockIdx.x * blockDim.x + threadIdx.x;
    if (idx < BV*HV) g_h[idx] = h0[idx];
}

__global__ void msum_k(const float* __restrict__ mask) {
    int t = blockIdx.x;
    float s = 0.f;
    for (int i = threadIdx.x; i < BV*FV; i += 256) {
        int b = i >> 8, f = i & 255;
        s += mask[(b*TV + t)*FV + f];
    }
    __shared__ float red[256];
    red[threadIdx.x] = s;
    __syncthreads();
    for (int st = 128; st > 0; st >>= 1) {
        if (threadIdx.x < st) red[threadIdx.x] += red[threadIdx.x + st];
        __syncthreads();
    }
    if (threadIdx.x == 0) g_msum[t] = red[0];
}

__global__ void gru_k(int t, float* __restrict__ hfin) {
    int idx = blockIdx.x * blockDim.x + threadIdx.x;  // B*H
    int b = idx >> 10, j = idx & 1023;
    float hd = g_h[idx] * g_gammaH[(size_t)t*BV*HV + idx];
    int base = b*3*HV + j;
    float r = 1.f / (1.f + expf(-(g_gi[base]        + g_gh[base])));
    float z = 1.f / (1.f + expf(-(g_gi[base + HV]   + g_gh[base + HV])));
    float n = tanhf(g_gi[base + 2*HV] + r * g_gh[base + 2*HV]);
    float hn = (1.f - z) * n + z * hd;
    g_h[idx] = hn;
    if (hfin) hfin[idx] = hn;
}

__global__ void final_k(float* __restrict__ out) {
    __shared__ float s[TV];
    int t = threadIdx.x;  // 64 threads
    float acc = 0.f;
    for (int i = 0; i < NB2; i++) acc += g_lossPart[t*NB2 + i];
    s[t] = acc / (g_msum[t] + 1e-12f);
    __syncthreads();
    if (t == 0) {
        float L = 0.f;
        for (int i = 0; i < TV; i++) L += s[i];
        out[OFF_LOSS]     = L;
        out[OFF_LOSS + 1] = 0.f;  // kl_loss
    }
}

// ---------------- launch ----------------

extern "C" void kernel_launch(void* const* d_in, const int* in_sizes, int n_in,
                              void* d_out, int out_size) {
    const float* x      = (const float*)d_in[0];
    const float* mask   = (const float*)d_in[1];
    const float* deltas = (const float*)d_in[2];
    const float* h0     = (const float*)d_in[3];
    const float* Wdh    = (const float*)d_in[4];
    const float* bdh    = (const float*)d_in[5];
    const float* Wdx    = (const float*)d_in[6];
    const float* bdx    = (const float*)d_in[7];
    const float* Wh     = (const float*)d_in[8];
    const float* bh     = (const float*)d_in[9];
    const float* Wfr    = (const float*)d_in[10];
    const float* bfr    = (const float*)d_in[11];
    const float* Wwc    = (const float*)d_in[12];
    const float* bwc    = (const float*)d_in[13];
    const float* Wih    = (const float*)d_in[14];
    const float* bih    = (const float*)d_in[15];
    const float* Whh    = (const float*)d_in[16];
    const float* bhh    = (const float*)d_in[17];

    float* out      = (float*)d_out;
    float* ximp_out = out;
    float* rec_out  = out + OFF_REC;
    float* hfin     = out + OFF_HFIN;

    hinit_k<<<(BV*HV)/256, 256>>>(h0);
    msum_k<<<TV, 256>>>(mask);

    // P1: gammaH, M=32768, N=1024, K=256  -> grid (8, 512)
    tgemm_k<64,128,16,32,32><<<dim3(1024/128, 32768/64), 256>>>(
        FV, AL_P1{deltas}, BL_P1{Wdh}, EP_P1{bdh});

    // P2: beta, M=32768, N=256, K=512 -> grid (2, 512)
    tgemm_k<64,128,16,32,32><<<dim3(256/128, 32768/64), 256>>>(
        2*FV, AL_P2{deltas, mask, Wdx, bdx}, BL_P2{Wwc}, EP_P2{bwc});

    for (int t = 0; t < TV; t++) {
        // G1: [x_h | gh], M=512, N=3328, K=1024 -> 26 x 8 = 208 blocks
        tgemm_k<64,128,16,32,32><<<dim3(3328/128, 512/64), 256>>>(
            HV, AL_G1{t}, BL_G1{Wh, Whh}, EP_G1{bh, bhh});

        // G2: xu + fused combine/imputation/loss, M=512, N=256, K=256 -> 4 x 8 = 32 blocks
        tgemm_k<64,64,16,32,16><<<dim3(256/64, 512/64), 256>>>(
            FV, AL_G2{x, mask, t}, BL_G2{Wfr},
            EP_G2{bfr, x, mask, rec_out, ximp_out, t});

        // G3: gi, M=512, N=3072, K=512 -> 24 x 8 = 192 blocks
        tgemm_k<64,128,16,32,32><<<dim3(3072/128, 512/64), 256>>>(
            2*FV, AL_G3{ximp_out, mask, t}, BL_G3{Wih}, EP_G3{bih});

        // GRU elementwise update
        gru_k<<<(BV*HV)/256, 256>>>(t, (t == TV-1) ? hfin : nullptr);
    }

    final_k<<<1, TV>>>(out);
}

// round 5
// speedup vs baseline: 2.3848x; 1.0288x over previous
#include <cuda_runtime.h>
#include <math.h>
#include <stdint.h>

// Problem constants
#define BV 512
#define TV 64
#define FV 256
#define HV 1024

// Output layout: x_imp [B,T,F] | reconstruction [B,T,F] | h_fin [B,H] | x_loss | kl_loss
#define OFF_REC   (BV*TV*FV)
#define OFF_HFIN  (2*BV*TV*FV)
#define OFF_LOSS  (2*BV*TV*FV + BV*HV)

#define NB2 32   // number of blocks in GEMM2 grid (loss partials per step)

// ---------------- scratch ----------------
__device__ float g_h[BV*HV];
__device__ float g_xh[BV*FV];
__device__ float g_gh[BV*3*HV];
__device__ float g_gi[BV*3*HV];
__device__ float g_gammaH[(size_t)TV*BV*HV];
__device__ float g_beta[(size_t)TV*BV*FV];
__device__ float g_msum[TV];
__device__ float g_lossPart[TV*NB2];

__device__ __forceinline__ uint32_t f2tf(float f) {
    uint32_t r;
    asm("cvt.rna.tf32.f32 %0, %1;" : "=r"(r) : "f"(f));
    return r;
}

// ------------- tf32 tensor-core GEMM with fragment-native smem layout -------------
// C[m,n] = sum_k A(m,k)*B(n,k), fused epilogue. 256 threads = 8 warps.
// A smem: uint4 per (m16-tile, k8-tile, lane) -> one LDS.128 per A fragment.
// B smem: uint2 per (n8-tile,  k8-tile, lane) -> one LDS.64  per B fragment.
template<int BM,int BN,int BK,int WM,int WN,class AL,class BL,class EP>
__global__ __launch_bounds__(256, 2)
void tgemm_k(int K, AL al, BL bl, EP ep) {
    constexpr int WARPS_M = BM/WM, WARPS_N = BN/WN;
    static_assert(WARPS_M*WARPS_N == 8, "need 8 warps");
    constexpr int MI = WM/16, NI = WN/8;
    constexpr int TH = 256;
    constexpr int AE = BM*BK/TH, BE = BN*BK/TH;
    constexpr int KT = BK/8;                  // k8-tiles per block tile

    __shared__ uint4 As4[2][(BM/16)*KT*32];
    __shared__ uint2 Bs2[2][(BN/8)*KT*32];

    const int tid = threadIdx.x;
    const int lane = tid & 31, wid = tid >> 5;
    const int wm = (wid % WARPS_M) * WM;
    const int wn = (wid / WARPS_M) * WN;
    const int gid = lane >> 2, tig = lane & 3;
    const int bm = blockIdx.y * BM, bn = blockIdx.x * BN;

    float acc[MI][NI][4];
    #pragma unroll
    for (int mi = 0; mi < MI; mi++)
        #pragma unroll
        for (int ni = 0; ni < NI; ni++)
            #pragma unroll
            for (int c = 0; c < 4; c++) acc[mi][ni][c] = 0.f;

    uint32_t ar[AE], br[BE];

    // permuted smem word index for A element (local m, local k)
    auto aidx = [&](int m, int k) -> int {
        int mt = m >> 4, r = m & 15, kt = k >> 3, c = k & 7;
        return (((mt*KT + kt)*32) + ((r & 7)*4 + (c & 3)))*4 + ((r >> 3) + ((c >> 2) << 1));
    };
    auto bidx = [&](int n, int k) -> int {
        int nt = n >> 3, r = n & 7, kt = k >> 3, c = k & 7;
        return (((nt*KT + kt)*32) + (r*4 + (c & 3)))*2 + (c >> 2);
    };

    // prologue: tile 0
    #pragma unroll
    for (int i = 0; i < AE; i++) { int e = tid + i*TH; ar[i] = f2tf(al(bm + e/BK, e%BK)); }
    #pragma unroll
    for (int i = 0; i < BE; i++) { int e = tid + i*TH; br[i] = f2tf(bl(bn + e/BK, e%BK)); }
    #pragma unroll
    for (int i = 0; i < AE; i++) { int e = tid + i*TH; ((uint32_t*)As4[0])[aidx(e/BK, e%BK)] = ar[i]; }
    #pragma unroll
    for (int i = 0; i < BE; i++) { int e = tid + i*TH; ((uint32_t*)Bs2[0])[bidx(e/BK, e%BK)] = br[i]; }
    __syncthreads();

    int cur = 0;
    for (int k0 = BK; k0 <= K; k0 += BK) {
        const bool more = (k0 < K);
        if (more) {
            #pragma unroll
            for (int i = 0; i < AE; i++) { int e = tid + i*TH; ar[i] = f2tf(al(bm + e/BK, k0 + e%BK)); }
            #pragma unroll
            for (int i = 0; i < BE; i++) { int e = tid + i*TH; br[i] = f2tf(bl(bn + e/BK, k0 + e%BK)); }
        }
        #pragma unroll
        for (int kk = 0; kk < KT; kk++) {
            uint4 av[MI];
            uint2 bv[NI];
            #pragma unroll
            for (int mi = 0; mi < MI; mi++)
                av[mi] = As4[cur][((wm/16 + mi)*KT + kk)*32 + lane];
            #pragma unroll
            for (int ni = 0; ni < NI; ni++)
                bv[ni] = Bs2[cur][((wn/8 + ni)*KT + kk)*32 + lane];
            #pragma unroll
            for (int mi = 0; mi < MI; mi++)
                #pragma unroll
                for (int ni = 0; ni < NI; ni++)
                    asm volatile(
                        "mma.sync.aligned.m16n8k8.row.col.f32.tf32.tf32.f32 "
                        "{%0,%1,%2,%3}, {%4,%5,%6,%7}, {%8,%9}, {%0,%1,%2,%3};"
                        : "+f"(acc[mi][ni][0]), "+f"(acc[mi][ni][1]),
                          "+f"(acc[mi][ni][2]), "+f"(acc[mi][ni][3])
                        : "r"(av[mi].x), "r"(av[mi].y), "r"(av[mi].z), "r"(av[mi].w),
                          "r"(bv[ni].x), "r"(bv[ni].y));
        }
        if (more) {
            #pragma unroll
            for (int i = 0; i < AE; i++) { int e = tid + i*TH; ((uint32_t*)As4[cur^1])[aidx(e/BK, e%BK)] = ar[i]; }
            #pragma unroll
            for (int i = 0; i < BE; i++) { int e = tid + i*TH; ((uint32_t*)Bs2[cur^1])[bidx(e/BK, e%BK)] = br[i]; }
        }
        __syncthreads();
        cur ^= 1;
    }

    float rsum = 0.f;
    #pragma unroll
    for (int mi = 0; mi < MI; mi++) {
        #pragma unroll
        for (int ni = 0; ni < NI; ni++) {
            int gm0 = bm + wm + mi*16 + gid;
            int gn0 = bn + wn + ni*8 + tig*2;
            rsum += ep(gm0,     gn0,     acc[mi][ni][0]);
            rsum += ep(gm0,     gn0 + 1, acc[mi][ni][1]);
            rsum += ep(gm0 + 8, gn0,     acc[mi][ni][2]);
            rsum += ep(gm0 + 8, gn0 + 1, acc[mi][ni][3]);
        }
    }

    if constexpr (EP::RED) {
        __shared__ float red[256];
        red[tid] = rsum;
        __syncthreads();
        for (int s = 128; s > 0; s >>= 1) {
            if (tid < s) red[tid] += red[tid + s];
            __syncthreads();
        }
        if (tid == 0) {
            int lin = blockIdx.y * gridDim.x + blockIdx.x;
            ep.store_partial(lin, red[0]);
        }
    }
}

// ---------------- functors ----------------

// P1: gammaH = exp(-relu(deltas @ Wdh^T + bdh)); M = T*B (m = t*B + b)
struct AL_P1 {
    const float* deltas;
    __device__ float operator()(int m, int k) const {
        int t = m >> 9, b = m & 511;
        return deltas[(b*TV + t)*FV + k];
    }
};
struct BL_P1 {
    const float* Wdh;
    __device__ float operator()(int n, int k) const { return Wdh[n*FV + k]; }
};
struct EP_P1 {
    const float* bdh;
    static constexpr bool RED = false;
    __device__ float operator()(int m, int n, float v) const {
        g_gammaH[(size_t)m*HV + n] = expf(-fmaxf(v + bdh[n], 0.f));
        return 0.f;
    }
    __device__ void store_partial(int, float) const {}
};

// P2: beta = [gamma_x, m] @ Wwc^T + bwc; gamma_x computed on the fly (diag decay)
struct AL_P2 {
    const float* deltas; const float* mask; const float* Wdx; const float* bdx;
    __device__ float operator()(int m, int k) const {
        int t = m >> 9, b = m & 511;
        if (k < FV) {
            float d = deltas[(b*TV + t)*FV + k];
            return expf(-fmaxf(d * Wdx[k*FV + k] + bdx[k], 0.f));
        }
        return mask[(b*TV + t)*FV + (k - FV)];
    }
};
struct BL_P2 {
    const float* Wwc;
    __device__ float operator()(int n, int k) const { return Wwc[n*(2*FV) + k]; }
};
struct EP_P2 {
    const float* bwc;
    static constexpr bool RED = false;
    __device__ float operator()(int m, int n, float v) const {
        g_beta[(size_t)m*FV + n] = v + bwc[n];
        return 0.f;
    }
    __device__ void store_partial(int, float) const {}
};

// G1: [x_h | gh] = (h * gammaH[t]) @ [Wh ; Whh]^T  (N = 3328, K = 1024)
struct AL_G1 {
    int t;
    __device__ float operator()(int m, int k) const {
        int idx = m*HV + k;
        return g_h[idx] * g_gammaH[(size_t)t*BV*HV + idx];
    }
};
struct BL_G1 {
    const float* Wh; const float* Whh;
    __device__ float operator()(int n, int k) const {
        return (n < FV) ? Wh[n*HV + k] : Whh[(n - FV)*HV + k];
    }
};
struct EP_G1 {
    const float* bh; const float* bhh;
    static constexpr bool RED = false;
    __device__ float operator()(int m, int n, float v) const {
        if (n < FV) g_xh[m*FV + n] = v + bh[n];
        else        g_gh[m*3*HV + (n - FV)] = v + bhh[n - FV];
        return 0.f;
    }
    __device__ void store_partial(int, float) const {}
};

// G2: xu = x_r @ Wfr_off^T + bfr ; epilogue: combine, imputation, loss partial
struct AL_G2 {
    const float* x; const float* mask; int t;
    __device__ float operator()(int m, int k) const {
        int idx = (m*TV + t)*FV + k;
        float mt = mask[idx];
        return mt * x[idx] + (1.f - mt) * g_xh[m*FV + k];
    }
};
struct BL_G2 {
    const float* Wfr;
    __device__ float operator()(int n, int k) const {
        return (n == k) ? 0.f : Wfr[n*FV + k];
    }
};
struct EP_G2 {
    const float* bfr; const float* x; const float* mask;
    float* rec; float* ximp; int t;
    static constexpr bool RED = true;
    __device__ float operator()(int m, int n, float v) const {
        float xu = v + bfr[n];
        float xh = g_xh[m*FV + n];
        float be = g_beta[(size_t)t*BV*FV + m*FV + n];
        float xc = be * xu + (1.f - be) * xh;
        int idx = (m*TV + t)*FV + n;
        float mt = mask[idx], xt = x[idx];
        rec[idx]  = xc;
        ximp[idx] = mt * xt + (1.f - mt) * xc;
        return fabsf(xc - xt) * mt;
    }
    __device__ void store_partial(int lin, float v) const {
        g_lossPart[t*NB2 + lin] = v;
    }
};

// G3: gi = [x_imp, m] @ Wih^T + bih  (K = 512)
struct AL_G3 {
    const float* ximp; const float* mask; int t;
    __device__ float operator()(int m, int k) const {
        if (k < FV) return ximp[(m*TV + t)*FV + k];
        return mask[(m*TV + t)*FV + (k - FV)];
    }
};
struct BL_G3 {
    const float* Wih;
    __device__ float operator()(int n, int k) const { return Wih[n*(2*FV) + k]; }
};
struct EP_G3 {
    const float* bih;
    static constexpr bool RED = false;
    __device__ float operator()(int m, int n, float v) const {
        g_gi[m*3*HV + n] = v + bih[n];
        return 0.f;
    }
    __device__ void store_partial(int, float) const {}
};

// ---------------- elementwise kernels ----------------

__global__ void hinit_k(const float* __restrict__ h0) {
    int idx = blockIdx.x * blockDim.x + threadIdx.x;
    if (idx < BV*HV) g_h[idx] = h0[idx];
}

__global__ void msum_k(const float* __restrict__ mask) {
    int t = blockIdx.x;
    float s = 0.f;
    for (int i = threadIdx.x; i < BV*FV; i += 256) {
        int b = i >> 8, f = i & 255;
        s += mask[(b*TV + t)*FV + f];
    }
    __shared__ float red[256];
    red[threadIdx.x] = s;
    __syncthreads();
    for (int st = 128; st > 0; st >>= 1) {
        if (threadIdx.x < st) red[threadIdx.x] += red[threadIdx.x + st];
        __syncthreads();
    }
    if (threadIdx.x == 0) g_msum[t] = red[0];
}

__global__ void gru_k(int t, float* __restrict__ hfin) {
    int idx = blockIdx.x * blockDim.x + threadIdx.x;  // B*H
    int b = idx >> 10, j = idx & 1023;
    float hd = g_h[idx] * g_gammaH[(size_t)t*BV*HV + idx];
    int base = b*3*HV + j;
    float r = 1.f / (1.f + expf(-(g_gi[base]        + g_gh[base])));
    float z = 1.f / (1.f + expf(-(g_gi[base + HV]   + g_gh[base + HV])));
    float n = tanhf(g_gi[base + 2*HV] + r * g_gh[base + 2*HV]);
    float hn = (1.f - z) * n + z * hd;
    g_h[idx] = hn;
    if (hfin) hfin[idx] = hn;
}

__global__ void final_k(float* __restrict__ out) {
    __shared__ float s[TV];
    int t = threadIdx.x;  // 64 threads
    float acc = 0.f;
    for (int i = 0; i < NB2; i++) acc += g_lossPart[t*NB2 + i];
    s[t] = acc / (g_msum[t] + 1e-12f);
    __syncthreads();
    if (t == 0) {
        float L = 0.f;
        for (int i = 0; i < TV; i++) L += s[i];
        out[OFF_LOSS]     = L;
        out[OFF_LOSS + 1] = 0.f;  // kl_loss
    }
}

// ---------------- launch ----------------

extern "C" void kernel_launch(void* const* d_in, const int* in_sizes, int n_in,
                              void* d_out, int out_size) {
    const float* x      = (const float*)d_in[0];
    const float* mask   = (const float*)d_in[1];
    const float* deltas = (const float*)d_in[2];
    const float* h0     = (const float*)d_in[3];
    const float* Wdh    = (const float*)d_in[4];
    const float* bdh    = (const float*)d_in[5];
    const float* Wdx    = (const float*)d_in[6];
    const float* bdx    = (const float*)d_in[7];
    const float* Wh     = (const float*)d_in[8];
    const float* bh     = (const float*)d_in[9];
    const float* Wfr    = (const float*)d_in[10];
    const float* bfr    = (const float*)d_in[11];
    const float* Wwc    = (const float*)d_in[12];
    const float* bwc    = (const float*)d_in[13];
    const float* Wih    = (const float*)d_in[14];
    const float* bih    = (const float*)d_in[15];
    const float* Whh    = (const float*)d_in[16];
    const float* bhh    = (const float*)d_in[17];

    float* out      = (float*)d_out;
    float* ximp_out = out;
    float* rec_out  = out + OFF_REC;
    float* hfin     = out + OFF_HFIN;

    hinit_k<<<(BV*HV)/256, 256>>>(h0);
    msum_k<<<TV, 256>>>(mask);

    // P1: gammaH, M=32768, N=1024, K=256
    tgemm_k<64,128,16,32,32><<<dim3(1024/128, 32768/64), 256>>>(
        FV, AL_P1{deltas}, BL_P1{Wdh}, EP_P1{bdh});

    // P2: beta, M=32768, N=256, K=512
    tgemm_k<64,128,16,32,32><<<dim3(256/128, 32768/64), 256>>>(
        2*FV, AL_P2{deltas, mask, Wdx, bdx}, BL_P2{Wwc}, EP_P2{bwc});

    for (int t = 0; t < TV; t++) {
        // G1: [x_h | gh], M=512, N=3328, K=1024 -> 208 blocks
        tgemm_k<64,128,16,32,32><<<dim3(3328/128, 512/64), 256>>>(
            HV, AL_G1{t}, BL_G1{Wh, Whh}, EP_G1{bh, bhh});

        // G2: xu + fused combine/imputation/loss, M=512, N=256, K=256 -> 32 blocks
        tgemm_k<64,64,16,32,16><<<dim3(256/64, 512/64), 256>>>(
            FV, AL_G2{x, mask, t}, BL_G2{Wfr},
            EP_G2{bfr, x, mask, rec_out, ximp_out, t});

        // G3: gi, M=512, N=3072, K=512 -> 192 blocks
        tgemm_k<64,128,16,32,32><<<dim3(3072/128, 512/64), 256>>>(
            2*FV, AL_G3{ximp_out, mask, t}, BL_G3{Wih}, EP_G3{bih});

        // GRU elementwise update
        gru_k<<<(BV*HV)/256, 256>>>(t, (t == TV-1) ? hfin : nullptr);
    }

    final_k<<<1, TV>>>(out);
}

// round 6
// speedup vs baseline: 3.2903x; 1.3797x over previous
#include <cuda_runtime.h>
#include <math.h>
#include <stdint.h>

// Problem constants
#define BV 512
#define TV 64
#define FV 256
#define HV 1024

// Output layout: x_imp [B,T,F] | reconstruction [B,T,F] | h_fin [B,H] | x_loss | kl_loss
#define OFF_REC   (BV*TV*FV)
#define OFF_HFIN  (2*BV*TV*FV)
#define OFF_LOSS  (2*BV*TV*FV + BV*HV)

#define NB2 32   // number of blocks in GEMM2 grid (loss partials per step)

// ---------------- scratch ----------------
__device__ float g_h[BV*HV];
__device__ float g_xh[BV*FV];
__device__ float g_gh[BV*3*HV];
__device__ float g_gi[BV*3*HV];
__device__ float g_gammaH[(size_t)TV*BV*HV];
__device__ float g_beta[(size_t)TV*BV*FV];
__device__ float g_msum[TV];
__device__ float g_lossPart[TV*NB2];

// Pre-swizzled tf32 weight buffers (uint2 fragment granularity)
#define SZ2(N,K) ((N)*(K)/2)
#define BOFF_G1 0
#define BOFF_G3 (BOFF_G1 + SZ2(3328,1024))
#define BOFF_G2 (BOFF_G3 + SZ2(3072,512))
#define BOFF_P1 (BOFF_G2 + SZ2(256,256))
#define BOFF_P2 (BOFF_P1 + SZ2(1024,256))
#define BSWZ_TOTAL (BOFF_P2 + SZ2(256,512))
__device__ uint2 g_Bswz[BSWZ_TOTAL];

__device__ __forceinline__ uint32_t f2tf(float f) {
    uint32_t r;
    asm("cvt.rna.tf32.f32 %0, %1;" : "=r"(r) : "f"(f));
    return r;
}

// ---------------- weight pre-swizzle: B(n,k) -> fragment-native tf32 ----------------
template<class BL>
__global__ void swz_k(int boff, int N, int K, BL bl) {
    int idx = blockIdx.x * 256 + threadIdx.x;
    if (idx >= N*K) return;
    int n = idx / K, k = idx % K;
    int KTT = K >> 3;
    uint32_t* d = (uint32_t*)(g_Bswz + boff);
    int off = (((n>>3)*KTT + (k>>3))*32 + ((n&7)*4 + (k&3)))*2 + ((k>>2)&1);
    d[off] = f2tf(bl(n, k));
}

// ------------- tf32 tensor-core GEMM, B streamed from pre-swizzled global -------------
// C[m,n] = sum_k A(m,k)*B(n,k). 256 threads = 8 warps. A via smem (fragment layout,
// LDS.128), B fragments one LDG.64 each straight from g_Bswz.
template<int BM,int BN,int BK,int WM,int WN,class AL,class EP>
__global__ __launch_bounds__(256, 2)
void tgemm2_k(int K, int KTT, int boff, AL al, EP ep) {
    constexpr int WARPS_M = BM/WM, WARPS_N = BN/WN;
    static_assert(WARPS_M*WARPS_N == 8, "need 8 warps");
    constexpr int MI = WM/16, NI = WN/8, KT = BK/8;
    constexpr int KQ = BK/4;                 // float4 per A row
    constexpr int AF4 = (BM*BK/4)/256;       // float4 per thread for A

    __shared__ uint4 As4[2][(BM/16)*KT*32];

    const uint2* __restrict__ Bg = g_Bswz + boff;
    const int tid = threadIdx.x, lane = tid & 31, wid = tid >> 5;
    const int wm = (wid % WARPS_M)*WM, wn = (wid / WARPS_M)*WN;
    const int gid = lane >> 2, tig = lane & 3;
    const int bm = blockIdx.y*BM, bn = blockIdx.x*BN;
    const int ntBase = (bn >> 3) + (wn >> 3);

    float acc[MI][NI][4];
    #pragma unroll
    for (int mi = 0; mi < MI; mi++)
        #pragma unroll
        for (int ni = 0; ni < NI; ni++)
            #pragma unroll
            for (int c = 0; c < 4; c++) acc[mi][ni][c] = 0.f;

    uint32_t aw[AF4][4];
    auto ldA = [&](int k0) {
        #pragma unroll
        for (int i = 0; i < AF4; i++) {
            int f = tid + i*256;
            int m = f / KQ, k4 = (f % KQ)*4;
            float4 v = al.load4(bm + m, k0 + k4);
            aw[i][0] = f2tf(v.x); aw[i][1] = f2tf(v.y);
            aw[i][2] = f2tf(v.z); aw[i][3] = f2tf(v.w);
        }
    };
    auto stA = [&](int buf) {
        uint32_t* s = (uint32_t*)As4[buf];
        #pragma unroll
        for (int i = 0; i < AF4; i++) {
            int f = tid + i*256;
            int m = f / KQ, k4 = (f % KQ)*4;
            int mt = m >> 4, r = m & 15, kt = k4 >> 3;
            int base = (((mt*KT + kt)*32) + ((r&7)*4))*4 + (r>>3) + (((k4>>2)&1)<<1);
            s[base]    = aw[i][0];
            s[base+4]  = aw[i][1];
            s[base+8]  = aw[i][2];
            s[base+12] = aw[i][3];
        }
    };

    ldA(0); stA(0);
    __syncthreads();

    int cur = 0;
    for (int k0 = 0; k0 < K; k0 += BK) {
        // B fragments for this tile: direct LDG.64 from pre-swizzled global
        uint2 bf[NI][KT];
        int ktg = k0 >> 3;
        #pragma unroll
        for (int ni = 0; ni < NI; ni++)
            #pragma unroll
            for (int kk = 0; kk < KT; kk++)
                bf[ni][kk] = Bg[((ntBase + ni)*KTT + ktg + kk)*32 + lane];

        const bool more = (k0 + BK) < K;
        if (more) ldA(k0 + BK);

        #pragma unroll
        for (int kk = 0; kk < KT; kk++) {
            uint4 av[MI];
            #pragma unroll
            for (int mi = 0; mi < MI; mi++)
                av[mi] = As4[cur][(((wm>>4) + mi)*KT + kk)*32 + lane];
            #pragma unroll
            for (int mi = 0; mi < MI; mi++)
                #pragma unroll
                for (int ni = 0; ni < NI; ni++)
                    asm volatile(
                        "mma.sync.aligned.m16n8k8.row.col.f32.tf32.tf32.f32 "
                        "{%0,%1,%2,%3}, {%4,%5,%6,%7}, {%8,%9}, {%0,%1,%2,%3};"
                        : "+f"(acc[mi][ni][0]), "+f"(acc[mi][ni][1]),
                          "+f"(acc[mi][ni][2]), "+f"(acc[mi][ni][3])
                        : "r"(av[mi].x), "r"(av[mi].y), "r"(av[mi].z), "r"(av[mi].w),
                          "r"(bf[ni][kk].x), "r"(bf[ni][kk].y));
        }
        if (more) stA(cur ^ 1);
        __syncthreads();
        cur ^= 1;
    }

    float rsum = 0.f;
    #pragma unroll
    for (int mi = 0; mi < MI; mi++) {
        #pragma unroll
        for (int ni = 0; ni < NI; ni++) {
            int gm0 = bm + wm + mi*16 + gid;
            int gn0 = bn + wn + ni*8 + tig*2;
            rsum += ep(gm0,     gn0,     acc[mi][ni][0]);
            rsum += ep(gm0,     gn0 + 1, acc[mi][ni][1]);
            rsum += ep(gm0 + 8, gn0,     acc[mi][ni][2]);
            rsum += ep(gm0 + 8, gn0 + 1, acc[mi][ni][3]);
        }
    }

    if constexpr (EP::RED) {
        __shared__ float red[256];
        red[tid] = rsum;
        __syncthreads();
        for (int s = 128; s > 0; s >>= 1) {
            if (tid < s) red[tid] += red[tid + s];
            __syncthreads();
        }
        if (tid == 0) {
            int lin = blockIdx.y * gridDim.x + blockIdx.x;
            ep.store_partial(lin, red[0]);
        }
    }
}

// ---------------- A-side loaders (float4, k aligned to 4) ----------------

struct AL_P1 {
    const float* deltas;
    __device__ float4 load4(int m, int k) const {
        int t = m >> 9, b = m & 511;
        return *(const float4*)&deltas[(b*TV + t)*FV + k];
    }
};
struct AL_P2 {
    const float* deltas; const float* mask; const float* Wdx; const float* bdx;
    __device__ float4 load4(int m, int k) const {
        int t = m >> 9, b = m & 511;
        if (k < FV) {
            float4 d = *(const float4*)&deltas[(b*TV + t)*FV + k];
            float4 bd = *(const float4*)&bdx[k];
            float4 r;
            r.x = expf(-fmaxf(d.x * Wdx[(k+0)*FV + (k+0)] + bd.x, 0.f));
            r.y = expf(-fmaxf(d.y * Wdx[(k+1)*FV + (k+1)] + bd.y, 0.f));
            r.z = expf(-fmaxf(d.z * Wdx[(k+2)*FV + (k+2)] + bd.z, 0.f));
            r.w = expf(-fmaxf(d.w * Wdx[(k+3)*FV + (k+3)] + bd.w, 0.f));
            return r;
        }
        return *(const float4*)&mask[(b*TV + t)*FV + (k - FV)];
    }
};
struct AL_G1 {
    int t;
    __device__ float4 load4(int m, int k) const {
        int idx = m*HV + k;
        float4 h4 = *(const float4*)&g_h[idx];
        float4 g4 = *(const float4*)&g_gammaH[(size_t)t*BV*HV + idx];
        return make_float4(h4.x*g4.x, h4.y*g4.y, h4.z*g4.z, h4.w*g4.w);
    }
};
struct AL_G2 {
    const float* x; const float* mask; int t;
    __device__ float4 load4(int m, int k) const {
        int idx = (m*TV + t)*FV + k;
        float4 mt = *(const float4*)&mask[idx];
        float4 xt = *(const float4*)&x[idx];
        float4 xh = *(const float4*)&g_xh[m*FV + k];
        return make_float4(mt.x*xt.x + (1.f-mt.x)*xh.x,
                           mt.y*xt.y + (1.f-mt.y)*xh.y,
                           mt.z*xt.z + (1.f-mt.z)*xh.z,
                           mt.w*xt.w + (1.f-mt.w)*xh.w);
    }
};
struct AL_G3 {
    const float* ximp; const float* mask; int t;
    __device__ float4 load4(int m, int k) const {
        if (k < FV) return *(const float4*)&ximp[(m*TV + t)*FV + k];
        return *(const float4*)&mask[(m*TV + t)*FV + (k - FV)];
    }
};

// ---------------- B-side scalar loaders (used only by swz_k) ----------------

struct BL_P1 {
    const float* Wdh;
    __device__ float operator()(int n, int k) const { return Wdh[n*FV + k]; }
};
struct BL_P2 {
    const float* Wwc;
    __device__ float operator()(int n, int k) const { return Wwc[n*(2*FV) + k]; }
};
struct BL_G1 {
    const float* Wh; const float* Whh;
    __device__ float operator()(int n, int k) const {
        return (n < FV) ? Wh[n*HV + k] : Whh[(n - FV)*HV + k];
    }
};
struct BL_G2 {
    const float* Wfr;
    __device__ float operator()(int n, int k) const {
        return (n == k) ? 0.f : Wfr[n*FV + k];
    }
};
struct BL_G3 {
    const float* Wih;
    __device__ float operator()(int n, int k) const { return Wih[n*(2*FV) + k]; }
};

// ---------------- epilogues ----------------

struct EP_P1 {
    const float* bdh;
    static constexpr bool RED = false;
    __device__ float operator()(int m, int n, float v) const {
        g_gammaH[(size_t)m*HV + n] = expf(-fmaxf(v + bdh[n], 0.f));
        return 0.f;
    }
    __device__ void store_partial(int, float) const {}
};
struct EP_P2 {
    const float* bwc;
    static constexpr bool RED = false;
    __device__ float operator()(int m, int n, float v) const {
        g_beta[(size_t)m*FV + n] = v + bwc[n];
        return 0.f;
    }
    __device__ void store_partial(int, float) const {}
};
struct EP_G1 {
    const float* bh; const float* bhh;
    static constexpr bool RED = false;
    __device__ float operator()(int m, int n, float v) const {
        if (n < FV) g_xh[m*FV + n] = v + bh[n];
        else        g_gh[m*3*HV + (n - FV)] = v + bhh[n - FV];
        return 0.f;
    }
    __device__ void store_partial(int, float) const {}
};
struct EP_G2 {
    const float* bfr; const float* x; const float* mask;
    float* rec; float* ximp; int t;
    static constexpr bool RED = true;
    __device__ float operator()(int m, int n, float v) const {
        float xu = v + bfr[n];
        float xh = g_xh[m*FV + n];
        float be = g_beta[(size_t)t*BV*FV + m*FV + n];
        float xc = be * xu + (1.f - be) * xh;
        int idx = (m*TV + t)*FV + n;
        float mt = mask[idx], xt = x[idx];
        rec[idx]  = xc;
        ximp[idx] = mt * xt + (1.f - mt) * xc;
        return fabsf(xc - xt) * mt;
    }
    __device__ void store_partial(int lin, float v) const {
        g_lossPart[t*NB2 + lin] = v;
    }
};
struct EP_G3 {
    const float* bih;
    static constexpr bool RED = false;
    __device__ float operator()(int m, int n, float v) const {
        g_gi[m*3*HV + n] = v + bih[n];
        return 0.f;
    }
    __device__ void store_partial(int, float) const {}
};

// ---------------- elementwise kernels ----------------

__global__ void hinit_k(const float* __restrict__ h0) {
    int idx = blockIdx.x * blockDim.x + threadIdx.x;
    if (idx < BV*HV) g_h[idx] = h0[idx];
}

__global__ void msum_k(const float* __restrict__ mask) {
    int t = blockIdx.x;
    float s = 0.f;
    for (int i = threadIdx.x; i < BV*FV; i += 256) {
        int b = i >> 8, f = i & 255;
        s += mask[(b*TV + t)*FV + f];
    }
    __shared__ float red[256];
    red[threadIdx.x] = s;
    __syncthreads();
    for (int st = 128; st > 0; st >>= 1) {
        if (threadIdx.x < st) red[threadIdx.x] += red[threadIdx.x + st];
        __syncthreads();
    }
    if (threadIdx.x == 0) g_msum[t] = red[0];
}

__global__ void gru_k(int t, float* __restrict__ hfin) {
    int idx = blockIdx.x * blockDim.x + threadIdx.x;  // B*H
    int b = idx >> 10, j = idx & 1023;
    float hd = g_h[idx] * g_gammaH[(size_t)t*BV*HV + idx];
    int base = b*3*HV + j;
    float r = 1.f / (1.f + expf(-(g_gi[base]        + g_gh[base])));
    float z = 1.f / (1.f + expf(-(g_gi[base + HV]   + g_gh[base + HV])));
    float n = tanhf(g_gi[base + 2*HV] + r * g_gh[base + 2*HV]);
    float hn = (1.f - z) * n + z * hd;
    g_h[idx] = hn;
    if (hfin) hfin[idx] = hn;
}

__global__ void final_k(float* __restrict__ out) {
    __shared__ float s[TV];
    int t = threadIdx.x;  // 64 threads
    float acc = 0.f;
    for (int i = 0; i < NB2; i++) acc += g_lossPart[t*NB2 + i];
    s[t] = acc / (g_msum[t] + 1e-12f);
    __syncthreads();
    if (t == 0) {
        float L = 0.f;
        for (int i = 0; i < TV; i++) L += s[i];
        out[OFF_LOSS]     = L;
        out[OFF_LOSS + 1] = 0.f;  // kl_loss
    }
}

// ---------------- launch ----------------

extern "C" void kernel_launch(void* const* d_in, const int* in_sizes, int n_in,
                              void* d_out, int out_size) {
    const float* x      = (const float*)d_in[0];
    const float* mask   = (const float*)d_in[1];
    const float* deltas = (const float*)d_in[2];
    const float* h0     = (const float*)d_in[3];
    const float* Wdh    = (const float*)d_in[4];
    const float* bdh    = (const float*)d_in[5];
    const float* Wdx    = (const float*)d_in[6];
    const float* bdx    = (const float*)d_in[7];
    const float* Wh     = (const float*)d_in[8];
    const float* bh     = (const float*)d_in[9];
    const float* Wfr    = (const float*)d_in[10];
    const float* bfr    = (const float*)d_in[11];
    const float* Wwc    = (const float*)d_in[12];
    const float* bwc    = (const float*)d_in[13];
    const float* Wih    = (const float*)d_in[14];
    const float* bih    = (const float*)d_in[15];
    const float* Whh    = (const float*)d_in[16];
    const float* bhh    = (const float*)d_in[17];

    float* out      = (float*)d_out;
    float* ximp_out = out;
    float* rec_out  = out + OFF_REC;
    float* hfin     = out + OFF_HFIN;

    hinit_k<<<(BV*HV)/256, 256>>>(h0);
    msum_k<<<TV, 256>>>(mask);

    // Pre-swizzle weight matrices into fragment-native tf32
    swz_k<<<(3328*1024 + 255)/256, 256>>>(BOFF_G1, 3328, 1024, BL_G1{Wh, Whh});
    swz_k<<<(3072*512  + 255)/256, 256>>>(BOFF_G3, 3072, 512,  BL_G3{Wih});
    swz_k<<<(256*256   + 255)/256, 256>>>(BOFF_G2, 256,  256,  BL_G2{Wfr});
    swz_k<<<(1024*256  + 255)/256, 256>>>(BOFF_P1, 1024, 256,  BL_P1{Wdh});
    swz_k<<<(256*512   + 255)/256, 256>>>(BOFF_P2, 256,  512,  BL_P2{Wwc});

    // P1: gammaH, M=32768, N=1024, K=256
    tgemm2_k<64,128,32,32,32><<<dim3(1024/128, 32768/64), 256>>>(
        FV, FV/8, BOFF_P1, AL_P1{deltas}, EP_P1{bdh});

    // P2: beta, M=32768, N=256, K=512
    tgemm2_k<64,128,32,32,32><<<dim3(256/128, 32768/64), 256>>>(
        2*FV, 2*FV/8, BOFF_P2, AL_P2{deltas, mask, Wdx, bdx}, EP_P2{bwc});

    for (int t = 0; t < TV; t++) {
        // G1: [x_h | gh], M=512, N=3328, K=1024 -> 208 blocks
        tgemm2_k<64,128,32,32,32><<<dim3(3328/128, 512/64), 256>>>(
            HV, HV/8, BOFF_G1, AL_G1{t}, EP_G1{bh, bhh});

        // G2: xu + fused combine/imputation/loss, M=512, N=256, K=256 -> 32 blocks
        tgemm2_k<64,64,32,32,16><<<dim3(256/64, 512/64), 256>>>(
            FV, FV/8, BOFF_G2, AL_G2{x, mask, t},
            EP_G2{bfr, x, mask, rec_out, ximp_out, t});

        // G3: gi, M=512, N=3072, K=512 -> 192 blocks
        tgemm2_k<64,128,32,32,32><<<dim3(3072/128, 512/64), 256>>>(
            2*FV, 2*FV/8, BOFF_G3, AL_G3{ximp_out, mask, t}, EP_G3{bih});

        // GRU elementwise update
        gru_k<<<(BV*HV)/256, 256>>>(t, (t == TV-1) ? hfin : nullptr);
    }

    final_k<<<1, TV>>>(out);
}